// round 7
// baseline (speedup 1.0000x reference)
#include <cuda_runtime.h>
#include <cuda_fp16.h>

// PairwisePotential1 — 8 px/thread, row-streamed half2 math + f16x2 EX2.
// out = w1 * first/9 + w2 * (4+4*sqrt2)/9
// first = 1 + sum_{8 fwd offsets (i,j)} exp2(K*diff^2 + K*d), K = -0.5*log2(e)
// v[i][k] = x(y-1+i, xo-1+k) with zero padding; centers = v[0][p].
// Pair packs: E[k]=(v[2k],v[2k+1]) via F2FP (fma pipe), O[k]=(v[2k+1],v[2k+2])
// via PRMT (alu pipe). Rows streamed: only row-0 centers persist.

#define S 128
#define SS (S * S)

__device__ __forceinline__ __half2 oshift(__half2 a, __half2 b) {
    // (high half of a, low half of b)
    unsigned ua = *reinterpret_cast<unsigned*>(&a);
    unsigned ub = *reinterpret_cast<unsigned*>(&b);
    unsigned r = __byte_perm(ua, ub, 0x5432);
    return *reinterpret_cast<__half2*>(&r);
}

__global__ __launch_bounds__(256) void pp_kernel(
    const float* __restrict__ x,
    const float* __restrict__ w1,
    const float* __restrict__ w2,
    float* __restrict__ out)
{
    int t  = blockIdx.x * blockDim.x + threadIdx.x;  // one thread = 8 consecutive x
    int xo = (t & 15) << 3;            // 0,8,...,120
    int y  = (t >> 4) & (S - 1);
    int bc = t >> 11;                  // b*C + c
    int c  = bc & 63;

    const float* __restrict__ xb = x + (size_t)bc * SS;

    const float Kf = -0.5f * 1.44269504088896340736f;   // -0.5*log2(e)
    const __half2 K2h = __float2half2_rn(Kf);
    const __half2 L1h = __float2half2_rn(Kf);                            // d = 1
    const __half2 L2h = __float2half2_rn(Kf * 1.41421356237309504880f);  // d = sqrt(2)

    __half2 accA[4], accB[4];
#pragma unroll
    for (int q = 0; q < 4; q++) {
        accA[q] = __float2half2_rn(1.0f);   // self term folded in
        accB[q] = __float2half2_rn(0.0f);
    }

#define LOADROW(E, O, RY, OK) {                                              \
        const float* __restrict__ rp = xb + (RY) * S + xo;                   \
        float4 A  = (OK) ? *(const float4*)(rp)     : make_float4(0,0,0,0);  \
        float4 Bv = (OK) ? *(const float4*)(rp + 4) : make_float4(0,0,0,0);  \
        float lf = ((OK) & (xo > 0))     ? __ldg(rp - 1) : 0.f;              \
        float rt = ((OK) & (xo + 8 < S)) ? __ldg(rp + 8) : 0.f;              \
        E[0] = __floats2half2_rn(lf,   A.x);                                 \
        E[1] = __floats2half2_rn(A.y,  A.z);                                 \
        E[2] = __floats2half2_rn(A.w,  Bv.x);                                \
        E[3] = __floats2half2_rn(Bv.y, Bv.z);                                \
        E[4] = __floats2half2_rn(Bv.w, rt);                                  \
        O[0] = oshift(E[0], E[1]);                                           \
        O[1] = oshift(E[1], E[2]);                                           \
        O[2] = oshift(E[2], E[3]);                                           \
        O[3] = oshift(E[3], E[4]); }

#define TERM(CV, N, LL, ACC) {                 \
        __half2 d_ = __hsub2((CV), (N));       \
        __half2 m_ = __hmul2(d_, K2h);         \
        __half2 a_ = __hfma2(m_, d_, (LL));    \
        ACC = __hadd2(ACC, h2exp2(a_)); }

    __half2 C[5];   // row-0 even packs = center pairs

    // ── row 0 (y-1): centers; offsets (0,1) d=1, (0,2) d=1
    {
        __half2 E[5], O[4];
        bool ok = (y > 0);
        LOADROW(E, O, (y - 1), ok)
#pragma unroll
        for (int q = 0; q < 4; q++) {
            TERM(E[q], O[q],     L1h, accA[q])
            TERM(E[q], E[q + 1], L1h, accA[q])
            C[q] = E[q];
        }
        C[4] = E[4];
    }
    // ── row 1 (y): always in-bounds; (1,0) d=1, (1,1)&(1,2) d=sqrt2
    {
        __half2 E[5], O[4];
        LOADROW(E, O, y, true)
#pragma unroll
        for (int q = 0; q < 4; q++) {
            TERM(C[q], E[q],     L1h, accA[q])
            TERM(C[q], O[q],     L2h, accB[q])
            TERM(C[q], E[q + 1], L2h, accB[q])
        }
    }
    // ── row 2 (y+1): (2,0) d=1, (2,1)&(2,2) d=sqrt2
    {
        __half2 E[5], O[4];
        bool ok = (y < S - 1);
        LOADROW(E, O, (y + 1), ok)
#pragma unroll
        for (int q = 0; q < 4; q++) {
            TERM(C[q], E[q],     L1h, accA[q])
            TERM(C[q], O[q],     L2h, accB[q])
            TERM(C[q], E[q + 1], L2h, accB[q])
        }
    }
#undef TERM
#undef LOADROW

    const float INV9   = 1.0f / 9.0f;
    const float SECOND = (4.0f + 4.0f * 1.41421356237309504880f) / 9.0f;

    int wbase = c * SS + y * S + xo;
    float4 w1a = *(const float4*)(w1 + wbase);
    float4 w1b = *(const float4*)(w1 + wbase + 4);
    float4 w2a = *(const float4*)(w2 + wbase);
    float4 w2b = *(const float4*)(w2 + wbase + 4);

    float f[8];
#pragma unroll
    for (int q = 0; q < 4; q++) {
        float2 fA = __half22float2(accA[q]);
        float2 fB = __half22float2(accB[q]);
        f[2 * q]     = fA.x + fB.x;
        f[2 * q + 1] = fA.y + fB.y;
    }

    float4 r0 = make_float4(
        fmaf(w1a.x, f[0] * INV9, w2a.x * SECOND),
        fmaf(w1a.y, f[1] * INV9, w2a.y * SECOND),
        fmaf(w1a.z, f[2] * INV9, w2a.z * SECOND),
        fmaf(w1a.w, f[3] * INV9, w2a.w * SECOND));
    float4 r1 = make_float4(
        fmaf(w1b.x, f[4] * INV9, w2b.x * SECOND),
        fmaf(w1b.y, f[5] * INV9, w2b.y * SECOND),
        fmaf(w1b.z, f[6] * INV9, w2b.z * SECOND),
        fmaf(w1b.w, f[7] * INV9, w2b.w * SECOND));

    float4* op = (float4*)(out + (size_t)t * 8);
    op[0] = r0;
    op[1] = r1;
}

extern "C" void kernel_launch(void* const* d_in, const int* in_sizes, int n_in,
                              void* d_out, int out_size)
{
    const float* x  = (const float*)d_in[0];
    const float* w1 = (const float*)d_in[1];
    const float* w2 = (const float*)d_in[2];
    float* out = (float*)d_out;

    int total8 = out_size >> 3;          // 8 pixels per thread
    int threads = 256;
    int blocks = (total8 + threads - 1) / threads;
    pp_kernel<<<blocks, threads>>>(x, w1, w2, out);
}

// round 8
// speedup vs baseline: 1.0593x; 1.0593x over previous
#include <cuda_runtime.h>
#include <cuda_fp16.h>

// PairwisePotential1 — warp-per-row coalesced, half2 math + f16x2 EX2.
// One warp = one (b,c,y) row of 128 px; lane l -> output cols 4l..4l+3.
// Window (original coords): centers = orig(y-1, x-1); values v_k = orig col
// 4l-1+k, k=0..5, rows y-1..y+1, zero padding. Halo via warp shuffle.
// first = 1 + sum exp2(K*diff^2 + K*d), K = -0.5*log2(e), d in {1, sqrt2}.

#define S 128
#define SS (S * S)

__global__ __launch_bounds__(256) void pp_kernel(
    const float* __restrict__ x,
    const float* __restrict__ w1,
    const float* __restrict__ w2,
    float* __restrict__ out)
{
    int t    = blockIdx.x * blockDim.x + threadIdx.x;
    int lane = t & 31;
    int R    = t >> 5;              // global row id = bc*128 + y
    int y    = R & (S - 1);
    int bc   = R >> 7;
    int c    = bc & 63;
    int x0   = lane << 2;           // output col base

    const float* __restrict__ rowc = x + (size_t)R * S + x0;   // row y, cols x0..x0+3

    const float Kf = -0.5f * 1.44269504088896340736f;   // -0.5*log2(e)
    const __half2 K2h = __float2half2_rn(Kf);
    const __half2 L1h = __float2half2_rn(Kf);                            // d=1
    const __half2 L2h = __float2half2_rn(Kf * 1.41421356237309504880f);  // d=sqrt2

    __half2 accA0 = __float2half2_rn(1.0f), accB0 = __float2half2_rn(0.0f);
    __half2 accA1 = __float2half2_rn(1.0f), accB1 = __float2half2_rn(0.0f);
    __half2 C0, C1;                 // center packs (row y-1): (v0,v1), (v2,v3)

#define TERM(CV, N, LL, ACC) {                 \
        __half2 d_ = __hsub2((CV), (N));       \
        __half2 m_ = __hmul2(d_, K2h);         \
        __half2 a_ = __hfma2(m_, d_, (LL));    \
        ACC = __hadd2(ACC, h2exp2(a_)); }

#define MAKEROW(RP, OK, H01, H12, H23, H34, H45) {                       \
        float4 m = (OK) ? *(const float4*)(RP) : make_float4(0,0,0,0);   \
        float lf = __shfl_up_sync(0xFFFFFFFFu, m.w, 1);                  \
        float rt = __shfl_down_sync(0xFFFFFFFFu, m.x, 1);                \
        if (lane == 0)  lf = 0.f;                                        \
        if (lane == 31) rt = 0.f;                                        \
        H01 = __floats2half2_rn(lf,  m.x);                               \
        H12 = __floats2half2_rn(m.x, m.y);                               \
        H23 = __floats2half2_rn(m.y, m.z);                               \
        H34 = __floats2half2_rn(m.z, m.w);                               \
        H45 = __floats2half2_rn(m.w, rt); }

    // ── row i=0 (orig row y-1): centers; terms j=1 (d=1), j=2 (d=1)
    {
        __half2 h01, h12, h23, h34, h45;
        MAKEROW(rowc - S, (y > 0), h01, h12, h23, h34, h45)
        C0 = h01; C1 = h23;
        TERM(C0, h12, L1h, accA0)   // pair0 j=1
        TERM(C0, h23, L1h, accA0)   // pair0 j=2
        TERM(C1, h34, L1h, accA1)   // pair1 j=1
        TERM(C1, h45, L1h, accA1)   // pair1 j=2
    }
    // ── row i=1 (orig row y, always in-bounds): j=0 d=1; j=1,2 d=sqrt2
    {
        __half2 h01, h12, h23, h34, h45;
        MAKEROW(rowc, true, h01, h12, h23, h34, h45)
        TERM(C0, h01, L1h, accA0)
        TERM(C0, h12, L2h, accB0)
        TERM(C0, h23, L2h, accB0)
        TERM(C1, h23, L1h, accA1)
        TERM(C1, h34, L2h, accB1)
        TERM(C1, h45, L2h, accB1)
    }
    // ── row i=2 (orig row y+1): j=0 d=1; j=1,2 d=sqrt2
    {
        __half2 h01, h12, h23, h34, h45;
        MAKEROW(rowc + S, (y < S - 1), h01, h12, h23, h34, h45)
        TERM(C0, h01, L1h, accA0)
        TERM(C0, h12, L2h, accB0)
        TERM(C0, h23, L2h, accB0)
        TERM(C1, h23, L1h, accA1)
        TERM(C1, h34, L2h, accB1)
        TERM(C1, h45, L2h, accB1)
    }
#undef MAKEROW
#undef TERM

    const float INV9   = 1.0f / 9.0f;
    const float SECOND = (4.0f + 4.0f * 1.41421356237309504880f) / 9.0f;

    int wbase = c * SS + y * S + x0;
    float4 w1v = *(const float4*)(w1 + wbase);
    float4 w2v = *(const float4*)(w2 + wbase);

    float2 f0 = __half22float2(__hadd2(accA0, accB0));
    float2 f1 = __half22float2(__hadd2(accA1, accB1));

    float4 o;
    o.x = fmaf(w1v.x, f0.x * INV9, w2v.x * SECOND);
    o.y = fmaf(w1v.y, f0.y * INV9, w2v.y * SECOND);
    o.z = fmaf(w1v.z, f1.x * INV9, w2v.z * SECOND);
    o.w = fmaf(w1v.w, f1.y * INV9, w2v.w * SECOND);

    ((float4*)out)[t] = o;
}

extern "C" void kernel_launch(void* const* d_in, const int* in_sizes, int n_in,
                              void* d_out, int out_size)
{
    const float* x  = (const float*)d_in[0];
    const float* w1 = (const float*)d_in[1];
    const float* w2 = (const float*)d_in[2];
    float* out = (float*)d_out;

    int total4 = out_size >> 2;          // 4 px per thread, warp per row
    int threads = 256;
    int blocks = (total4 + threads - 1) / threads;
    pp_kernel<<<blocks, threads>>>(x, w1, w2, out);
}

// round 9
// speedup vs baseline: 1.1241x; 1.0612x over previous
#include <cuda_runtime.h>
#include <cuda_fp16.h>

// PairwisePotential1 — warp-coalesced, 2 output rows x 4 cols per thread,
// half-domain packing (PRMT) + 2-op prescaled TERM + f16x2 EX2.
// out = w1 * first/9 + w2 * (4+4*sqrt2)/9
// first = 1 + sum_{8 fwd offsets} exp2(-(s*diff)^2 + L), s = sqrt(0.5*log2e),
// L = K*d, K = -0.5*log2(e), d in {1, sqrt2}. Zero padding.
// Lane l covers cols 4l..4l+3; warp covers 128 cols x 2 output rows.

#define S 128
#define SS (S * S)
#define FULLM 0xFFFFFFFFu

__device__ __forceinline__ __half2 H2(unsigned u) {
    return *reinterpret_cast<__half2*>(&u);
}
__device__ __forceinline__ unsigned U2(__half2 h) {
    return *reinterpret_cast<unsigned*>(&h);
}

struct Row { unsigned h01, h12, h23, h34, h45; };  // (v0,v1)..(v4,v5)

__global__ __launch_bounds__(256) void pp_kernel(
    const float* __restrict__ x,
    const float* __restrict__ w1,
    const float* __restrict__ w2,
    float* __restrict__ out)
{
    int t    = blockIdx.x * blockDim.x + threadIdx.x;
    int lane = t & 31;
    int w    = t >> 5;              // warp id
    int y0   = (w & 63) << 1;       // first output row (0,2,...,126)
    int bc   = w >> 6;
    int c    = bc & 63;
    int x0   = lane << 2;

    const float* __restrict__ xb = x + (size_t)bc * SS + x0;

    const float sF = 0.84933300468f;                      // sqrt(0.5*log2e)
    const __half2 Sp  = __float2half2_rn(sF);
    const __half2 Sn  = __float2half2_rn(-sF);
    const float Kf = -0.5f * 1.44269504088896340736f;
    const __half2 L1h = __float2half2_rn(Kf);                            // d=1
    const __half2 L2h = __float2half2_rn(Kf * 1.41421356237309504880f);  // d=sqrt2

    // Load one orig row (cols x0-1..x0+4 via shuffle halo), build 5 packs.
#define LOADROW(RW, RY, OK) {                                            \
        float4 m = make_float4(0.f, 0.f, 0.f, 0.f);                      \
        if (OK) m = *(const float4*)(xb + (RY) * S);                     \
        unsigned p12 = U2(__floats2half2_rn(m.x, m.y));                  \
        unsigned p34 = U2(__floats2half2_rn(m.z, m.w));                  \
        unsigned nb = __shfl_up_sync(FULLM, p34, 1);                     \
        unsigned nd = __shfl_down_sync(FULLM, p12, 1);                   \
        if (lane == 0)  nb = 0u;                                         \
        if (lane == 31) nd = 0u;                                         \
        RW.h12 = p12; RW.h34 = p34;                                      \
        RW.h01 = __byte_perm(nb,  p12, 0x5432);                          \
        RW.h23 = __byte_perm(p12, p34, 0x5432);                          \
        RW.h45 = __byte_perm(p34, nd,  0x5432); }

    // TERM: ds = s*(C-N) via fma(N,-s,cs); a = L - ds^2; acc += exp2(a)
#define TERM(CS, N, LL, ACC) {                           \
        __half2 ds = __hfma2(H2(N), Sn, (CS));           \
        __half2 a_ = __hfma2(__hneg2(ds), ds, (LL));     \
        ACC = __hadd2(ACC, h2exp2(a_)); }

    // One output row: centers from R0 (h01, h23), neighbors R0,R1,R2.
#define OUTROW(R0, R1, R2, F)  {                                         \
        __half2 cs0 = __hmul2(Sp, H2(R0.h01));                           \
        __half2 cs1 = __hmul2(Sp, H2(R0.h23));                           \
        __half2 a0 = __float2half2_rn(1.0f), b0 = __float2half2_rn(0.0f);\
        __half2 a1 = __float2half2_rn(1.0f), b1 = __float2half2_rn(0.0f);\
        TERM(cs0, R0.h12, L1h, a0)  TERM(cs0, R0.h23, L1h, a0)           \
        TERM(cs0, R1.h01, L1h, a0)  TERM(cs0, R2.h01, L1h, a0)           \
        TERM(cs0, R1.h12, L2h, b0)  TERM(cs0, R1.h23, L2h, b0)           \
        TERM(cs0, R2.h12, L2h, b0)  TERM(cs0, R2.h23, L2h, b0)           \
        TERM(cs1, R0.h34, L1h, a1)  TERM(cs1, R0.h45, L1h, a1)           \
        TERM(cs1, R1.h23, L1h, a1)  TERM(cs1, R2.h23, L1h, a1)           \
        TERM(cs1, R1.h34, L2h, b1)  TERM(cs1, R1.h45, L2h, b1)           \
        TERM(cs1, R2.h34, L2h, b1)  TERM(cs1, R2.h45, L2h, b1)           \
        float2 fa0 = __half22float2(a0), fb0 = __half22float2(b0);       \
        float2 fa1 = __half22float2(a1), fb1 = __half22float2(b1);       \
        F[0] = fa0.x + fb0.x;  F[1] = fa0.y + fb0.y;                     \
        F[2] = fa1.x + fb1.x;  F[3] = fa1.y + fb1.y; }

    Row R0, R1, R2, R3;
    LOADROW(R0, (y0 - 1), (y0 > 0))        // orig row y0-1
    LOADROW(R1, y0, true)                  // orig row y0
    LOADROW(R2, (y0 + 1), true)            // orig row y0+1 (y0<=126 -> in bounds)

    float fA[4];
    OUTROW(R0, R1, R2, fA)                 // output row y0

    LOADROW(R3, (y0 + 2), (y0 + 2 < S))    // orig row y0+2
    float fB[4];
    OUTROW(R1, R2, R3, fB)                 // output row y0+1

#undef OUTROW
#undef TERM
#undef LOADROW

    const float INV9   = 1.0f / 9.0f;
    const float SECOND = (4.0f + 4.0f * 1.41421356237309504880f) / 9.0f;

    size_t obase = (size_t)bc * SS + (size_t)y0 * S + x0;
    const float* w1p = w1 + c * SS + y0 * S + x0;
    const float* w2p = w2 + c * SS + y0 * S + x0;

    {
        float4 w1v = *(const float4*)(w1p);
        float4 w2v = *(const float4*)(w2p);
        float4 o;
        o.x = fmaf(w1v.x, fA[0] * INV9, w2v.x * SECOND);
        o.y = fmaf(w1v.y, fA[1] * INV9, w2v.y * SECOND);
        o.z = fmaf(w1v.z, fA[2] * INV9, w2v.z * SECOND);
        o.w = fmaf(w1v.w, fA[3] * INV9, w2v.w * SECOND);
        *(float4*)(out + obase) = o;
    }
    {
        float4 w1v = *(const float4*)(w1p + S);
        float4 w2v = *(const float4*)(w2p + S);
        float4 o;
        o.x = fmaf(w1v.x, fB[0] * INV9, w2v.x * SECOND);
        o.y = fmaf(w1v.y, fB[1] * INV9, w2v.y * SECOND);
        o.z = fmaf(w1v.z, fB[2] * INV9, w2v.z * SECOND);
        o.w = fmaf(w1v.w, fB[3] * INV9, w2v.w * SECOND);
        *(float4*)(out + obase + S) = o;
    }
}

extern "C" void kernel_launch(void* const* d_in, const int* in_sizes, int n_in,
                              void* d_out, int out_size)
{
    const float* x  = (const float*)d_in[0];
    const float* w1 = (const float*)d_in[1];
    const float* w2 = (const float*)d_in[2];
    float* out = (float*)d_out;

    int total8 = out_size >> 3;          // 8 px per thread (2 rows x 4 cols)
    int threads = 256;
    int blocks = (total8 + threads - 1) / threads;
    pp_kernel<<<blocks, threads>>>(x, w1, w2, out);
}